// round 10
// baseline (speedup 1.0000x reference)
#include <cuda_runtime.h>

#define BB 16
#define LL 2048
#define HH 1024
#define ZZ 512

// Scratch (device globals; no allocation allowed)
__device__ float g_k[BB * HH];          // final @ Wk
__device__ float g_kq[BB * HH];         // Wq @ k
__device__ float g_w[BB * LL];          // RAW masked logits
__device__ float g_part[32 * BB * ZZ];  // partial column sums of latent z
__device__ float g_S2[8 * BB * ZZ];     // split-K partials of S
__device__ float g_M[BB];               // per-batch softmax max
__device__ float g_I[BB];               // per-batch softmax 1/sum

// Intra-launch dependency counters (zero at load; reset by resetter block)
__device__ unsigned g_acnt;             // kA blocks done (128)
__device__ unsigned g_bcnt;             // kB blocks done (128)
__device__ unsigned g_zcnt[BB];         // z-sum chunks per batch (32)
__device__ unsigned g_lcnt[BB];         // logit blocks per batch (128)
__device__ unsigned g_fcnt[BB];         // kF slices per batch (8)
__device__ unsigned g_scnt[BB];         // stats done per batch (1)
__device__ unsigned g_wpass;            // writers past their gates (5120)

// Block layout (single launch, 512 threads everywhere):
//   [0,128)      kA
//   [128,256)    kB      (waits g_acnt==128)
//   [256,768)    kE      z-sum
//   [768,896)    kF      (waits g_zcnt[b]==32)
//   [896,2944)   kC      logits, batch-ordered (waits g_bcnt==128)
//   [2944,2960)  stats   (waits g_lcnt[b]==128)
//   [2960,8080)  writers batch-ordered: per batch 256 attn + 64 out tiles
//   8080         resetter (waits g_wpass==5120)
#define WR0 2960

__global__ void __launch_bounds__(512) k_mega(
    const float* __restrict__ fin, const float* __restrict__ Wk,
    const float* __restrict__ Wq,  const float* __restrict__ Wv,
    const float* __restrict__ zin, const float* __restrict__ enc,
    const int* __restrict__ mask,  float* __restrict__ out)
{
    __shared__ __align__(16) float smem[8 * HH];   // 32 KB, aliased per stage
    const int blk = blockIdx.x;
    const int t = threadIdx.x;

    if (blk < 128) {
        // ---------------- kA ----------------
        float* sh  = smem;
        float* red = smem + HH;
        const int b = blk >> 3;
        const int hof = t & 127;
        const int h = ((blk & 7) << 7) + hof;
        const int cs = t >> 7;
        for (int j = t; j < HH; j += 512) sh[j] = fin[b * HH + j];
        __syncthreads();
        float acc = 0.f;
        const float* wcol = Wk + h;
#pragma unroll 8
        for (int c = cs * 256; c < (cs + 1) * 256; ++c)
            acc += sh[c] * wcol[(size_t)c * HH];
        red[t] = acc;
        __syncthreads();
        if (cs == 0) {
            g_k[b * HH + h] = red[hof] + red[128 + hof] + red[256 + hof] + red[384 + hof];
            __threadfence();
        }
        __syncthreads();
        if (t == 0) atomicAdd(&g_acnt, 1u);

    } else if (blk < 256) {
        // ---------------- kB (waits kA) ----------------
        if (t == 0) {
            while (*(volatile unsigned*)&g_acnt < 128u) {}
            __threadfence();
        }
        __syncthreads();
        float* sk = smem;
        const int e = blk - 128;
        const int rb = e >> 1;
        const int bg = e & 1;
        for (int j = t; j < 8 * HH; j += 512)
            sk[j] = *(volatile const float*)&g_k[(8 * bg + (j >> 10)) * HH + (j & 1023)];
        __syncthreads();

        const int warp = t >> 5, lane = t & 31;
        const int r = rb * 16 + warp;
        const float4* wrow = (const float4*)(Wq + (size_t)r * HH);
        float acc[8] = {0.f, 0.f, 0.f, 0.f, 0.f, 0.f, 0.f, 0.f};
#pragma unroll 2
        for (int c = lane; c < HH / 4; c += 32) {
            const float4 wv = wrow[c];
#pragma unroll
            for (int j = 0; j < 8; ++j) {
                const float4 kv = ((const float4*)(sk + j * HH))[c];
                acc[j] += wv.x * kv.x + wv.y * kv.y + wv.z * kv.z + wv.w * kv.w;
            }
        }
#pragma unroll
        for (int j = 0; j < 8; ++j) {
            float a = acc[j];
#pragma unroll
            for (int o = 16; o; o >>= 1) a += __shfl_xor_sync(0xffffffffu, a, o);
            if (lane == 0) g_kq[(8 * bg + j) * HH + r] = a;
        }
        if (lane == 0) __threadfence();
        __syncthreads();
        if (t == 0) atomicAdd(&g_bcnt, 1u);

    } else if (blk < 768) {
        // ---------------- kE: z-sum ----------------
        const int e = blk - 256;
        const int b = e >> 5;
        const int chunk = e & 31;
        const float* base = zin + ((size_t)b * LL + (size_t)chunk * 64) * ZZ + t;
        float acc = 0.f;
#pragma unroll 16
        for (int i = 0; i < 64; ++i) acc += __ldcs(base + (size_t)i * ZZ);
        g_part[(chunk * BB + b) * ZZ + t] = acc;
        __threadfence();
        __syncthreads();
        if (t == 0) atomicAdd(&g_zcnt[b], 1u);

    } else if (blk < 896) {
        // ---------------- kF: split-K S2 (waits kE[b]) ----------------
        const int e = blk - 768;
        const int b = e >> 3;
        const int slice = e & 7;
        if (t == 0) {
            while (*(volatile unsigned*)&g_zcnt[b] < 32u) {}
            __threadfence();
        }
        __syncthreads();

        float* zs = smem;
        const int cl = t >> 3;
        const int sub = t & 7;
        const int c = 64 * slice + cl;
        float a = 0.f;
#pragma unroll
        for (int j = 0; j < 4; ++j)
            a += *(volatile const float*)&g_part[((sub + 8 * j) * BB + b) * ZZ + c];
#pragma unroll
        for (int o = 4; o; o >>= 1) a += __shfl_xor_sync(0xffffffffu, a, o);
        if (sub == 0) zs[cl] = a;
        __syncthreads();

        float s = 0.f;
        const float* wbase = Wv + (size_t)(64 * slice) * ZZ + t;
#pragma unroll 8
        for (int c2 = 0; c2 < 64; ++c2)
            s += zs[c2] * wbase[(size_t)c2 * ZZ];
        g_S2[(slice * BB + b) * ZZ + t] = s;
        __threadfence();
        __syncthreads();
        if (t == 0) atomicAdd(&g_fcnt[b], 1u);

    } else if (blk < 2944) {
        // ---------------- kC: logits (waits kB), batch-ordered ----------------
        if (t == 0) {
            while (*(volatile unsigned*)&g_bcnt < 128u) {}
            __threadfence();
        }
        __syncthreads();

        const int warp = t >> 5, lane = t & 31;
        const int row = (blk - 896) * 16 + warp;
        const int b = row >> 11;
        const float4* e4 = (const float4*)(enc + (size_t)row * HH);
        const float4* kq4 = (const float4*)(g_kq + b * HH);
        float acc = 0.f;
#pragma unroll
        for (int c = lane; c < HH / 4; c += 32) {
            float4 ev = __ldcs(&e4[c]);
            float4 kv = __ldg(&kq4[c]);
            acc += ev.x * kv.x + ev.y * kv.y + ev.z * kv.z + ev.w * kv.w;
        }
#pragma unroll
        for (int o = 16; o; o >>= 1) acc += __shfl_xor_sync(0xffffffffu, acc, o);
        if (lane == 0) {
            float val = acc * 0.03125f;
            if (mask[row] == 0) val = -1e9f;
            g_w[row] = val;
            __threadfence();
        }
        __syncthreads();
        if (t == 0) atomicAdd(&g_lcnt[b], 1u);

    } else if (blk < WR0) {
        // ---------------- stats: per-batch softmax (M, 1/sum) ----------------
        __shared__ float red[16];
        __shared__ float s_max;
        const int b = blk - 2944;
        if (t == 0) {
            while (*(volatile unsigned*)&g_lcnt[b] < 128u) {}
            __threadfence();
        }
        __syncthreads();

        const int warp = t >> 5, lane = t & 31;
        float lg[4];
#pragma unroll
        for (int k = 0; k < 4; ++k)
            lg[k] = *(volatile const float*)&g_w[b * LL + k * 512 + t];

        float m = fmaxf(fmaxf(lg[0], lg[1]), fmaxf(lg[2], lg[3]));
#pragma unroll
        for (int o = 16; o; o >>= 1) m = fmaxf(m, __shfl_xor_sync(0xffffffffu, m, o));
        if (lane == 0) red[warp] = m;
        __syncthreads();
        if (warp == 0 && lane < 16) {
            float v = red[lane];
#pragma unroll
            for (int o = 8; o; o >>= 1) v = fmaxf(v, __shfl_xor_sync(0xffffu, v, o));
            if (lane == 0) s_max = v;
        }
        __syncthreads();
        const float M = s_max;

        float s = 0.f;
#pragma unroll
        for (int k = 0; k < 4; ++k) s += __expf(lg[k] - M);
#pragma unroll
        for (int o = 16; o; o >>= 1) s += __shfl_xor_sync(0xffffffffu, s, o);
        __syncthreads();
        if (lane == 0) red[warp] = s;
        __syncthreads();
        if (warp == 0 && lane == 0) {
            float v = 0.f;
#pragma unroll
            for (int i = 0; i < 16; ++i) v += red[i];
            g_M[b] = M;
            g_I[b] = 1.f / v;
            __threadfence();
            atomicAdd(&g_scnt[b], 1u);
        }

    } else if (blk < 8080) {
        // ---------------- writers: per-batch 256 attn + 64 out tiles ----------
        const int wblk = blk - WR0;
        const int b = wblk / 320;
        const int r = wblk - b * 320;
        const bool is_attn = (r < 256);

        if (t == 0) {
            if (is_attn) {
                while (*(volatile unsigned*)&g_scnt[b] < 1u) {}
            } else {
                while (*(volatile unsigned*)&g_scnt[b] < 1u) {}
                while (*(volatile unsigned*)&g_fcnt[b] < 8u) {}
            }
            __threadfence();
            atomicAdd(&g_wpass, 1u);
        }
        __syncthreads();
        const float M   = *(volatile const float*)&g_M[b];
        const float inv = *(volatile const float*)&g_I[b];

        if (is_attn) {
            const long long base = (long long)b * (LL * LL / 4) + (long long)r * 4096;
            const int rowbase = b * LL + r * 8;
            float4* attn4 = (float4*)(out + (size_t)BB * LL * ZZ);
            float w8[8];
#pragma unroll
            for (int j = 0; j < 8; ++j)
                w8[j] = __expf(*(volatile const float*)&g_w[rowbase + j] - M) * inv;
#pragma unroll
            for (int k = 0; k < 8; ++k) {
                const float wv = w8[k];
                __stcs(attn4 + base + k * 512 + t, make_float4(wv, wv, wv, wv));
            }
        } else {
            const int r2 = r - 256;
            const long long base = (long long)b * (LL * ZZ / 4) + (long long)r2 * 4096;
            const int rowbase = b * LL + r2 * 32;
            const int rsub = t >> 7;           // 0..3
            const int col = t & 127;
            const float4* S24 = (const float4*)g_S2;
            float4 sv = make_float4(0.f, 0.f, 0.f, 0.f);
#pragma unroll
            for (int k = 0; k < 8; ++k) {
                const float4 p = __ldcg(&S24[(k * BB + b) * (ZZ / 4) + col]);
                sv.x += p.x; sv.y += p.y; sv.z += p.z; sv.w += p.w;
            }
#pragma unroll
            for (int k = 0; k < 8; ++k) {
                const int row = rowbase + 4 * k + rsub;
                const float wv = __expf(*(volatile const float*)&g_w[row] - M) * inv;
                __stcs((float4*)out + base + k * 512 + t,
                       make_float4(wv * sv.x, wv * sv.y, wv * sv.z, wv * sv.w));
            }
        }

    } else {
        // ---------------- resetter: restore counters for next replay --------
        if (t == 0) {
            while (*(volatile unsigned*)&g_wpass < 5120u) {}
            g_acnt = 0u;
            g_bcnt = 0u;
#pragma unroll
            for (int i = 0; i < BB; ++i) {
                g_zcnt[i] = 0u; g_lcnt[i] = 0u;
                g_fcnt[i] = 0u; g_scnt[i] = 0u;
            }
            g_wpass = 0u;
            __threadfence();
        }
    }
}

// ---------------------------------------------------------------------------
extern "C" void kernel_launch(void* const* d_in, const int* in_sizes, int n_in,
                              void* d_out, int out_size)
{
    const float* enc  = (const float*)d_in[0];
    const float* fin  = (const float*)d_in[1];
    const float* zseq = (const float*)d_in[2];
    const int*   mask = (const int*)  d_in[3];
    const float* Wq   = (const float*)d_in[4];
    const float* Wk   = (const float*)d_in[5];
    const float* Wv   = (const float*)d_in[6];
    float* out = (float*)d_out;

    k_mega<<<8081, 512>>>(fin, Wk, Wq, Wv, zseq, enc, mask, out);
}

// round 11
// speedup vs baseline: 1.0342x; 1.0342x over previous
#include <cuda_runtime.h>

#define BB 16
#define LL 2048
#define HH 1024
#define ZZ 512

// Scratch (device globals; no allocation allowed)
__device__ float g_k[BB * HH];          // final @ Wk
__device__ float g_kq[BB * HH];         // Wq @ k
__device__ float g_w[BB * LL];          // RAW masked logits (softmax done in k5)
__device__ float g_part[32 * BB * ZZ];  // partial column sums of latent z
__device__ float g_S2[8 * BB * ZZ];     // split-K partials of S (reduced in k5)

// ---------------------------------------------------------------------------
// kE helper: one block = one (batch, 64-row chunk) partial column sum of z.
// ---------------------------------------------------------------------------
__device__ __forceinline__ void zsum_block(const float* __restrict__ zin, int e, int t)
{
    const int b = e >> 5;
    const int chunk = e & 31;
    const float* base = zin + ((size_t)b * LL + (size_t)chunk * 64) * ZZ + t;
    float acc = 0.f;
#pragma unroll 16
    for (int i = 0; i < 64; ++i) acc += __ldcs(base + (size_t)i * ZZ);
    g_part[(chunk * BB + b) * ZZ + t] = acc;
}

// ---------------------------------------------------------------------------
// L1: blocks [0,128)   -> kA: k[b,h] = fin[b,:] . Wk[:,h]
//     blocks [128,384) -> kE chunks [0,256)
// ---------------------------------------------------------------------------
__global__ void __launch_bounds__(512) k1_a_e(
    const float* __restrict__ fin, const float* __restrict__ Wk,
    const float* __restrict__ zin)
{
    __shared__ float sh[HH];
    __shared__ float red[512];
    const int blk = blockIdx.x;
    const int t = threadIdx.x;

    if (blk < 128) {
        const int b = blk >> 3;
        const int hof = t & 127;
        const int h = ((blk & 7) << 7) + hof;
        const int cs = t >> 7;
        for (int j = t; j < HH; j += 512) sh[j] = fin[b * HH + j];
        __syncthreads();
        float acc = 0.f;
        const float* wcol = Wk + h;
#pragma unroll 8
        for (int c = cs * 256; c < (cs + 1) * 256; ++c)
            acc += sh[c] * wcol[(size_t)c * HH];
        red[t] = acc;
        __syncthreads();
        if (cs == 0)
            g_k[b * HH + h] = red[hof] + red[128 + hof] + red[256 + hof] + red[384 + hof];
    } else {
        zsum_block(zin, blk - 128, t);
    }
}

// ---------------------------------------------------------------------------
// L2: blocks [0,128)   -> kB batch-shared (8 k-vectors in smem per block)
//     blocks [128,384) -> kE chunks [256,512)
// ---------------------------------------------------------------------------
__global__ void __launch_bounds__(512) k2_b_e(
    const float* __restrict__ Wq, const float* __restrict__ zin)
{
    __shared__ __align__(16) float sk[8 * HH];      // 32 KB
    const int blk = blockIdx.x;
    const int t = threadIdx.x;

    if (blk < 128) {
        const int rb = blk >> 1;
        const int bg = blk & 1;
        for (int j = t; j < 8 * HH; j += 512)
            sk[j] = g_k[(8 * bg + (j >> 10)) * HH + (j & 1023)];
        __syncthreads();

        const int warp = t >> 5, lane = t & 31;
        const int r = rb * 16 + warp;
        const float4* wrow = (const float4*)(Wq + (size_t)r * HH);
        float acc[8] = {0.f, 0.f, 0.f, 0.f, 0.f, 0.f, 0.f, 0.f};
#pragma unroll 2
        for (int c = lane; c < HH / 4; c += 32) {
            const float4 wv = wrow[c];
#pragma unroll
            for (int j = 0; j < 8; ++j) {
                const float4 kv = ((const float4*)(sk + j * HH))[c];
                acc[j] += wv.x * kv.x + wv.y * kv.y + wv.z * kv.z + wv.w * kv.w;
            }
        }
#pragma unroll
        for (int j = 0; j < 8; ++j) {
            float a = acc[j];
#pragma unroll
            for (int o = 16; o; o >>= 1) a += __shfl_xor_sync(0xffffffffu, a, o);
            if (lane == 0) g_kq[(8 * bg + j) * HH + r] = a;
        }
    } else {
        zsum_block(zin, 256 + (blk - 128), t);
    }
}

// ---------------------------------------------------------------------------
// k3 piece: blocks [0,512)  -> logits for rows [row0, row0+8192) (4 batches)
//           blocks [512,..) -> kF split-K (only piece 0 launches these)
// ---------------------------------------------------------------------------
__global__ void __launch_bounds__(512) k3_piece(
    const float* __restrict__ enc, const int* __restrict__ mask,
    const float* __restrict__ Wv, int row0)
{
    __shared__ float zs[64];
    const int blk = blockIdx.x;
    const int t = threadIdx.x;

    if (blk < 512) {
        const int warp = t >> 5, lane = t & 31;
        const int row = row0 + blk * 16 + warp;
        const int b = row >> 11;
        const float4* e4 = (const float4*)(enc + (size_t)row * HH);
        const float4* kq4 = (const float4*)(g_kq + b * HH);
        float acc = 0.f;
#pragma unroll
        for (int c = lane; c < HH / 4; c += 32) {
            float4 ev = __ldcs(&e4[c]);
            float4 kv = __ldg(&kq4[c]);
            acc += ev.x * kv.x + ev.y * kv.y + ev.z * kv.z + ev.w * kv.w;
        }
#pragma unroll
        for (int o = 16; o; o >>= 1) acc += __shfl_xor_sync(0xffffffffu, acc, o);
        if (lane == 0) {
            float val = acc * 0.03125f;
            if (mask[row] == 0) val = -1e9f;
            g_w[row] = val;
        }
    } else {
        const int e = blk - 512;         // 0..127 (piece 0 only)
        const int b = e >> 3;
        const int slice = e & 7;

        const int cl = t >> 3;
        const int sub = t & 7;
        const int c = 64 * slice + cl;
        float a = 0.f;
#pragma unroll
        for (int j = 0; j < 4; ++j)
            a += g_part[((sub + 8 * j) * BB + b) * ZZ + c];
#pragma unroll
        for (int o = 4; o; o >>= 1) a += __shfl_xor_sync(0xffffffffu, a, o);
        if (sub == 0) zs[cl] = a;
        __syncthreads();

        float s = 0.f;
        const float* wbase = Wv + (size_t)(64 * slice) * ZZ + t;
#pragma unroll 8
        for (int c2 = 0; c2 < 64; ++c2)
            s += zs[c2] * wbase[(size_t)c2 * ZZ];
        g_S2[(slice * BB + b) * ZZ + t] = s;
    }
}

// ---------------------------------------------------------------------------
// k5 piece: writers for 4 batches [b0, b0+4). 1280 blocks x 256 threads.
//   blocks [0,1024)    : attn (256/batch)
//   blocks [1024,1280) : out  (64/batch)
// R8's proven preamble (softmax stats recomputed per block, free under stores).
// ---------------------------------------------------------------------------
__global__ void __launch_bounds__(256) k5_piece(float* __restrict__ out, int b0)
{
    __shared__ float red[8];
    __shared__ float s_max, s_inv;
    const int blk = blockIdx.x;
    const int t = threadIdx.x;
    const int warp = t >> 5, lane = t & 31;

    const bool is_attn = (blk < 1024);
    const int b = b0 + (is_attn ? (blk >> 8) : ((blk - 1024) >> 6));

    // ---- softmax stats over this batch's 2048 raw logits ----
    float lg[8];
#pragma unroll
    for (int k = 0; k < 8; ++k) lg[k] = __ldg(&g_w[b * LL + k * 256 + t]);

    float m = lg[0];
#pragma unroll
    for (int k = 1; k < 8; ++k) m = fmaxf(m, lg[k]);
#pragma unroll
    for (int o = 16; o; o >>= 1) m = fmaxf(m, __shfl_xor_sync(0xffffffffu, m, o));
    if (lane == 0) red[warp] = m;
    __syncthreads();
    if (warp == 0 && lane < 8) {
        float v = red[lane];
#pragma unroll
        for (int o = 4; o; o >>= 1) v = fmaxf(v, __shfl_xor_sync(0xffu, v, o));
        if (lane == 0) s_max = v;
    }
    __syncthreads();
    const float M = s_max;

    float s = 0.f;
#pragma unroll
    for (int k = 0; k < 8; ++k) s += __expf(lg[k] - M);   // masked rows -> 0
#pragma unroll
    for (int o = 16; o; o >>= 1) s += __shfl_xor_sync(0xffffffffu, s, o);
    __syncthreads();
    if (lane == 0) red[warp] = s;
    __syncthreads();
    if (warp == 0 && lane < 8) {
        float v = red[lane];
#pragma unroll
        for (int o = 4; o; o >>= 1) v += __shfl_xor_sync(0xffu, v, o);
        if (lane == 0) s_inv = 1.f / v;
    }
    __syncthreads();
    const float inv = s_inv;

    // ---- 16 streaming float4 stores per thread ----
    if (is_attn) {
        const long long base = (long long)b * (LL * LL / 4)
                             + (long long)(blk & 255) * 4096;
        const int rowbase = (int)(base >> 9);
        float4* attn4 = (float4*)(out + (size_t)BB * LL * ZZ);
        float w8[8];
#pragma unroll
        for (int j = 0; j < 8; ++j)
            w8[j] = __expf(__ldg(&g_w[rowbase + j]) - M) * inv;
#pragma unroll
        for (int k = 0; k < 16; ++k) {
            const float wv = w8[k >> 1];
            __stcs(attn4 + base + k * 256 + t, make_float4(wv, wv, wv, wv));
        }
    } else {
        const int e = blk - 1024;
        const long long base = (long long)b * (LL * ZZ / 4)
                             + (long long)(e & 63) * 4096;
        const int rowbase = (int)(base >> 7);
        const int rsub = t >> 7;
        const int col = t & 127;
        const float4* S24 = (const float4*)g_S2;
        float4 sv = make_float4(0.f, 0.f, 0.f, 0.f);
#pragma unroll
        for (int k = 0; k < 8; ++k) {
            const float4 p = __ldg(&S24[(k * BB + b) * (ZZ / 4) + col]);
            sv.x += p.x; sv.y += p.y; sv.z += p.z; sv.w += p.w;
        }
#pragma unroll
        for (int k = 0; k < 16; ++k) {
            const float wv = __expf(__ldg(&g_w[rowbase + 2 * k + rsub]) - M) * inv;
            __stcs((float4*)out + base + k * 256 + t,
                   make_float4(wv * sv.x, wv * sv.y, wv * sv.z, wv * sv.w));
        }
    }
}

// ---------------------------------------------------------------------------
extern "C" void kernel_launch(void* const* d_in, const int* in_sizes, int n_in,
                              void* d_out, int out_size)
{
    const float* enc  = (const float*)d_in[0];
    const float* fin  = (const float*)d_in[1];
    const float* zseq = (const float*)d_in[2];
    const int*   mask = (const int*)  d_in[3];
    const float* Wq   = (const float*)d_in[4];
    const float* Wk   = (const float*)d_in[5];
    const float* Wv   = (const float*)d_in[6];
    float* out = (float*)d_out;

    cudaStream_t s1;
    cudaStreamCreateWithFlags(&s1, cudaStreamNonBlocking);
    cudaEvent_t ev[4], e_join;
    for (int i = 0; i < 4; ++i) cudaEventCreateWithFlags(&ev[i], cudaEventDisableTiming);
    cudaEventCreateWithFlags(&e_join, cudaEventDisableTiming);

    // stream0: producers (reads), batch-ordered pieces
    k1_a_e<<<384, 512>>>(fin, Wk, zseq);                  // kA + z-sum half 1
    k2_b_e<<<384, 512>>>(Wq, zseq);                       // kB + z-sum half 2
    for (int i = 0; i < 4; ++i) {
        k3_piece<<<(i == 0 ? 640 : 512), 512>>>(enc, mask, Wv, i * 8192);
        cudaEventRecord(ev[i], 0);
        cudaStreamWaitEvent(s1, ev[i], 0);
        k5_piece<<<1280, 256, 0, s1>>>(out, 4 * i);       // stream1: writers
    }

    // join side stream back into capture stream
    cudaEventRecord(e_join, s1);
    cudaStreamWaitEvent(0, e_join, 0);

    for (int i = 0; i < 4; ++i) cudaEventDestroy(ev[i]);
    cudaEventDestroy(e_join);
    cudaStreamDestroy(s1);
}

// round 12
// speedup vs baseline: 1.1877x; 1.1484x over previous
#include <cuda_runtime.h>

#define BB 16
#define LL 2048
#define HH 1024
#define ZZ 512

// Scratch (device globals; no allocation allowed)
__device__ float g_k[BB * HH];          // final @ Wk
__device__ float g_kq[BB * HH];         // Wq @ k
__device__ float g_w[BB * LL];          // RAW masked logits (softmax done in k5)
__device__ float g_part[32 * BB * ZZ];  // partial column sums of latent z
__device__ float g_S2[8 * BB * ZZ];     // split-K partials of S (reduced in k5)

// ---------------------------------------------------------------------------
// z-sum block (float4, high MLP): block = (batch, 64-row chunk).
// 512 threads = 4 row-groups x 128 float4-columns; 16 independent float4
// loads per thread; cross-rowgroup reduce in smem.
// ---------------------------------------------------------------------------
__device__ __forceinline__ void zsum_block_v4(
    const float* __restrict__ zin, int e, int t, float4* sred /* [3*128] */)
{
    const int b = e >> 5;
    const int chunk = e & 31;
    const int sub = t >> 7;              // 0..3
    const int col4 = t & 127;
    const float4* base = (const float4*)zin
        + ((size_t)b * LL + (size_t)chunk * 64 + sub) * (ZZ / 4) + col4;
    float4 acc = make_float4(0.f, 0.f, 0.f, 0.f);
#pragma unroll
    for (int i = 0; i < 16; ++i) {
        const float4 v = __ldcs(base + (size_t)i * ZZ);   // 4 rows per step
        acc.x += v.x; acc.y += v.y; acc.z += v.z; acc.w += v.w;
    }
    if (sub > 0) sred[(sub - 1) * 128 + col4] = acc;
    __syncthreads();
    if (sub == 0) {
#pragma unroll
        for (int j = 0; j < 3; ++j) {
            const float4 p = sred[j * 128 + col4];
            acc.x += p.x; acc.y += p.y; acc.z += p.z; acc.w += p.w;
        }
        ((float4*)g_part)[(chunk * BB + b) * (ZZ / 4) + col4] = acc;
    }
}

// ---------------------------------------------------------------------------
// L1: blocks [0,128)   -> kA: k[b,h] = fin[b,:] . Wk[:,h]
//     blocks [128,384) -> z-sum chunks [0,256)
// ---------------------------------------------------------------------------
__global__ void __launch_bounds__(512) k1_a_e(
    const float* __restrict__ fin, const float* __restrict__ Wk,
    const float* __restrict__ zin)
{
    __shared__ __align__(16) float smem[1536 + 512];   // kA: sh[1024]+red[512]; zE: 3*128 float4
    const int blk = blockIdx.x;
    const int t = threadIdx.x;

    if (blk < 128) {
        float* sh = smem;
        float* red = smem + HH;
        const int b = blk >> 3;
        const int hof = t & 127;
        const int h = ((blk & 7) << 7) + hof;
        const int cs = t >> 7;
        for (int j = t; j < HH; j += 512) sh[j] = fin[b * HH + j];
        __syncthreads();
        float acc = 0.f;
        const float* wcol = Wk + h;
#pragma unroll 8
        for (int c = cs * 256; c < (cs + 1) * 256; ++c)
            acc += sh[c] * wcol[(size_t)c * HH];
        red[t] = acc;
        __syncthreads();
        if (cs == 0)
            g_k[b * HH + h] = red[hof] + red[128 + hof] + red[256 + hof] + red[384 + hof];
    } else {
        zsum_block_v4(zin, blk - 128, t, (float4*)smem);
    }
}

// ---------------------------------------------------------------------------
// L2: blocks [0,128)   -> kB batch-shared (8 k-vectors in smem per block)
//     blocks [128,384) -> z-sum chunks [256,512)
// ---------------------------------------------------------------------------
__global__ void __launch_bounds__(512) k2_b_e(
    const float* __restrict__ Wq, const float* __restrict__ zin)
{
    __shared__ __align__(16) float sk[8 * HH];      // 32 KB (aliased for z reduce)
    const int blk = blockIdx.x;
    const int t = threadIdx.x;

    if (blk < 128) {
        const int rb = blk >> 1;
        const int bg = blk & 1;
        for (int j = t; j < 8 * HH; j += 512)
            sk[j] = g_k[(8 * bg + (j >> 10)) * HH + (j & 1023)];
        __syncthreads();

        const int warp = t >> 5, lane = t & 31;
        const int r = rb * 16 + warp;
        const float4* wrow = (const float4*)(Wq + (size_t)r * HH);
        float acc[8] = {0.f, 0.f, 0.f, 0.f, 0.f, 0.f, 0.f, 0.f};
#pragma unroll 2
        for (int c = lane; c < HH / 4; c += 32) {
            const float4 wv = wrow[c];
#pragma unroll
            for (int j = 0; j < 8; ++j) {
                const float4 kv = ((const float4*)(sk + j * HH))[c];
                acc[j] += wv.x * kv.x + wv.y * kv.y + wv.z * kv.z + wv.w * kv.w;
            }
        }
#pragma unroll
        for (int j = 0; j < 8; ++j) {
            float a = acc[j];
#pragma unroll
            for (int o = 16; o; o >>= 1) a += __shfl_xor_sync(0xffffffffu, a, o);
            if (lane == 0) g_kq[(8 * bg + j) * HH + r] = a;
        }
    } else {
        zsum_block_v4(zin, 256 + (blk - 128), t, (float4*)sk);
    }
}

// ---------------------------------------------------------------------------
// L3: blocks [0,1024)      -> logits, 2 rows per warp (MLP 16), 32 rows/block
//     blocks [1024,1152)   -> kF split-K: S2[slice,b,t] over 64-c slices
// ---------------------------------------------------------------------------
__global__ void __launch_bounds__(512) k3_logits_f(
    const float* __restrict__ enc, const int* __restrict__ mask,
    const float* __restrict__ Wv)
{
    __shared__ float zs[64];
    const int blk = blockIdx.x;
    const int t = threadIdx.x;

    if (blk < 1024) {
        const int warp = t >> 5, lane = t & 31;
        const int row = (blk * 16 + warp) * 2;          // rows row, row+1 (same batch)
        const int b = row >> 11;
        const float4* e40 = (const float4*)(enc + (size_t)row * HH);
        const float4* e41 = (const float4*)(enc + (size_t)(row + 1) * HH);
        const float4* kq4 = (const float4*)(g_kq + b * HH);
        float acc0 = 0.f, acc1 = 0.f;
#pragma unroll
        for (int c = lane; c < HH / 4; c += 32) {
            const float4 ev0 = __ldcs(&e40[c]);
            const float4 ev1 = __ldcs(&e41[c]);
            const float4 kv = __ldg(&kq4[c]);
            acc0 += ev0.x * kv.x + ev0.y * kv.y + ev0.z * kv.z + ev0.w * kv.w;
            acc1 += ev1.x * kv.x + ev1.y * kv.y + ev1.z * kv.z + ev1.w * kv.w;
        }
#pragma unroll
        for (int o = 16; o; o >>= 1) {
            acc0 += __shfl_xor_sync(0xffffffffu, acc0, o);
            acc1 += __shfl_xor_sync(0xffffffffu, acc1, o);
        }
        if (lane == 0) {
            float v0 = acc0 * 0.03125f;
            float v1 = acc1 * 0.03125f;
            if (mask[row] == 0)     v0 = -1e9f;
            if (mask[row + 1] == 0) v1 = -1e9f;
            g_w[row]     = v0;
            g_w[row + 1] = v1;
        }
    } else {
        const int e = blk - 1024;        // 0..127
        const int b = e >> 3;
        const int slice = e & 7;

        const int cl = t >> 3;           // 0..63
        const int sub = t & 7;           // 0..7
        const int c = 64 * slice + cl;
        float a = 0.f;
#pragma unroll
        for (int j = 0; j < 4; ++j)
            a += g_part[((sub + 8 * j) * BB + b) * ZZ + c];
#pragma unroll
        for (int o = 4; o; o >>= 1) a += __shfl_xor_sync(0xffffffffu, a, o);
        if (sub == 0) zs[cl] = a;
        __syncthreads();

        float s = 0.f;
        const float* wbase = Wv + (size_t)(64 * slice) * ZZ + t;
#pragma unroll 8
        for (int c2 = 0; c2 < 64; ++c2)
            s += zs[c2] * wbase[(size_t)c2 * ZZ];
        g_S2[(slice * BB + b) * ZZ + t] = s;
    }
}

// ---------------------------------------------------------------------------
// k5: fused softmax + S-reduce + streaming writer (unchanged from R8 best).
// 5120 blocks x 256 threads, 16 float4 stores per thread.
// ---------------------------------------------------------------------------
__global__ void __launch_bounds__(256) k5_write(float* __restrict__ out)
{
    __shared__ float red[8];
    __shared__ float s_max, s_inv;
    const int blk = blockIdx.x;
    const int t = threadIdx.x;
    const int warp = t >> 5, lane = t & 31;

    const bool is_attn = (blk < 4096);
    const int b = is_attn ? (blk >> 8) : ((blk - 4096) >> 6);

    float lg[8];
#pragma unroll
    for (int k = 0; k < 8; ++k) lg[k] = __ldg(&g_w[b * LL + k * 256 + t]);

    float m = lg[0];
#pragma unroll
    for (int k = 1; k < 8; ++k) m = fmaxf(m, lg[k]);
#pragma unroll
    for (int o = 16; o; o >>= 1) m = fmaxf(m, __shfl_xor_sync(0xffffffffu, m, o));
    if (lane == 0) red[warp] = m;
    __syncthreads();
    if (warp == 0 && lane < 8) {
        float v = red[lane];
#pragma unroll
        for (int o = 4; o; o >>= 1) v = fmaxf(v, __shfl_xor_sync(0xffu, v, o));
        if (lane == 0) s_max = v;
    }
    __syncthreads();
    const float M = s_max;

    float s = 0.f;
#pragma unroll
    for (int k = 0; k < 8; ++k) s += __expf(lg[k] - M);
#pragma unroll
    for (int o = 16; o; o >>= 1) s += __shfl_xor_sync(0xffffffffu, s, o);
    __syncthreads();
    if (lane == 0) red[warp] = s;
    __syncthreads();
    if (warp == 0 && lane < 8) {
        float v = red[lane];
#pragma unroll
        for (int o = 4; o; o >>= 1) v += __shfl_xor_sync(0xffu, v, o);
        if (lane == 0) s_inv = 1.f / v;
    }
    __syncthreads();
    const float inv = s_inv;

    if (is_attn) {
        const long long base = (long long)b * (LL * LL / 4)
                             + (long long)(blk & 255) * 4096;
        const int rowbase = (int)(base >> 9);
        float4* attn4 = (float4*)(out + (size_t)BB * LL * ZZ);
        float w8[8];
#pragma unroll
        for (int j = 0; j < 8; ++j)
            w8[j] = __expf(__ldg(&g_w[rowbase + j]) - M) * inv;
#pragma unroll
        for (int k = 0; k < 16; ++k) {
            const float wv = w8[k >> 1];
            __stcs(attn4 + base + k * 256 + t, make_float4(wv, wv, wv, wv));
        }
    } else {
        const int e = blk - 4096;
        const long long base = (long long)b * (LL * ZZ / 4)
                             + (long long)(e & 63) * 4096;
        const int rowbase = (int)(base >> 7);
        const int rsub = t >> 7;
        const int col = t & 127;
        const float4* S24 = (const float4*)g_S2;
        float4 sv = make_float4(0.f, 0.f, 0.f, 0.f);
#pragma unroll
        for (int k = 0; k < 8; ++k) {
            const float4 p = __ldg(&S24[(k * BB + b) * (ZZ / 4) + col]);
            sv.x += p.x; sv.y += p.y; sv.z += p.z; sv.w += p.w;
        }
#pragma unroll
        for (int k = 0; k < 16; ++k) {
            const float wv = __expf(__ldg(&g_w[rowbase + 2 * k + rsub]) - M) * inv;
            __stcs((float4*)out + base + k * 256 + t,
                   make_float4(wv * sv.x, wv * sv.y, wv * sv.z, wv * sv.w));
        }
    }
}

// ---------------------------------------------------------------------------
extern "C" void kernel_launch(void* const* d_in, const int* in_sizes, int n_in,
                              void* d_out, int out_size)
{
    const float* enc  = (const float*)d_in[0];
    const float* fin  = (const float*)d_in[1];
    const float* zseq = (const float*)d_in[2];
    const int*   mask = (const int*)  d_in[3];
    const float* Wq   = (const float*)d_in[4];
    const float* Wk   = (const float*)d_in[5];
    const float* Wv   = (const float*)d_in[6];
    float* out = (float*)d_out;

    k1_a_e<<<384, 512>>>(fin, Wk, zseq);       // kA + z-sum half 1 (float4)
    k2_b_e<<<384, 512>>>(Wq, zseq);            // kB + z-sum half 2 (float4)
    k3_logits_f<<<1152, 512>>>(enc, mask, Wv); // logits (2 rows/warp) + kF
    k5_write<<<5120, 256>>>(out);              // softmax + S-reduce + write
}

// round 13
// speedup vs baseline: 1.1917x; 1.0034x over previous
#include <cuda_runtime.h>

#define BB 16
#define LL 2048
#define HH 1024
#define ZZ 512

// Scratch (device globals; no allocation allowed)
__device__ float g_k[BB * HH];          // final @ Wk
__device__ float g_kq[BB * HH];         // Wq @ k
__device__ float g_w[BB * LL];          // RAW masked logits (softmax done in k5)
__device__ float g_part[32 * BB * ZZ];  // partial column sums of latent z
__device__ float g_S2[8 * BB * ZZ];     // split-K partials of S

// Intra-k5 dependency counters (zero at load; reset by k1 each run)
__device__ unsigned g_zcnt[BB];         // z-sum chunks done per batch (32)
__device__ unsigned g_fcnt[BB];         // kF slices done per batch (8)

// ---------------------------------------------------------------------------
// k1: pure kA. 128 blocks x 512 threads. Block 0 also resets k5 counters.
// ---------------------------------------------------------------------------
__global__ void __launch_bounds__(512) k1_a(
    const float* __restrict__ fin, const float* __restrict__ Wk)
{
    __shared__ float sh[HH];
    __shared__ float red[512];
    const int blk = blockIdx.x;
    const int t = threadIdx.x;

    if (blk == 0 && t == 0) {
#pragma unroll
        for (int i = 0; i < BB; ++i) { g_zcnt[i] = 0u; g_fcnt[i] = 0u; }
    }

    const int b = blk >> 3;
    const int hof = t & 127;
    const int h = ((blk & 7) << 7) + hof;
    const int cs = t >> 7;
    for (int j = t; j < HH; j += 512) sh[j] = fin[b * HH + j];
    __syncthreads();
    float acc = 0.f;
    const float* wcol = Wk + h;
#pragma unroll 8
    for (int c = cs * 256; c < (cs + 1) * 256; ++c)
        acc += sh[c] * wcol[(size_t)c * HH];
    red[t] = acc;
    __syncthreads();
    if (cs == 0)
        g_k[b * HH + h] = red[hof] + red[128 + hof] + red[256 + hof] + red[384 + hof];
}

// ---------------------------------------------------------------------------
// k2: pure kB batch-shared. 128 blocks x 512 threads.
// ---------------------------------------------------------------------------
__global__ void __launch_bounds__(512) k2_b(const float* __restrict__ Wq)
{
    __shared__ __align__(16) float sk[8 * HH];      // 32 KB
    const int blk = blockIdx.x;
    const int t = threadIdx.x;
    const int rb = blk >> 1;
    const int bg = blk & 1;
    for (int j = t; j < 8 * HH; j += 512)
        sk[j] = g_k[(8 * bg + (j >> 10)) * HH + (j & 1023)];
    __syncthreads();

    const int warp = t >> 5, lane = t & 31;
    const int r = rb * 16 + warp;
    const float4* wrow = (const float4*)(Wq + (size_t)r * HH);
    float acc[8] = {0.f, 0.f, 0.f, 0.f, 0.f, 0.f, 0.f, 0.f};
#pragma unroll 2
    for (int c = lane; c < HH / 4; c += 32) {
        const float4 wv = wrow[c];
#pragma unroll
        for (int j = 0; j < 8; ++j) {
            const float4 kv = ((const float4*)(sk + j * HH))[c];
            acc[j] += wv.x * kv.x + wv.y * kv.y + wv.z * kv.z + wv.w * kv.w;
        }
    }
#pragma unroll
    for (int j = 0; j < 8; ++j) {
        float a = acc[j];
#pragma unroll
        for (int o = 16; o; o >>= 1) a += __shfl_xor_sync(0xffffffffu, a, o);
        if (lane == 0) g_kq[(8 * bg + j) * HH + r] = a;
    }
}

// ---------------------------------------------------------------------------
// k3: pure logits, 2 rows per warp. 1024 blocks x 512 threads.
// ---------------------------------------------------------------------------
__global__ void __launch_bounds__(512) k3_logits(
    const float* __restrict__ enc, const int* __restrict__ mask)
{
    const int warp = threadIdx.x >> 5, lane = threadIdx.x & 31;
    const int row = (blockIdx.x * 16 + warp) * 2;
    const int b = row >> 11;
    const float4* e40 = (const float4*)(enc + (size_t)row * HH);
    const float4* e41 = (const float4*)(enc + (size_t)(row + 1) * HH);
    const float4* kq4 = (const float4*)(g_kq + b * HH);
    float acc0 = 0.f, acc1 = 0.f;
#pragma unroll
    for (int c = lane; c < HH / 4; c += 32) {
        const float4 ev0 = __ldcs(&e40[c]);
        const float4 ev1 = __ldcs(&e41[c]);
        const float4 kv = __ldg(&kq4[c]);
        acc0 += ev0.x * kv.x + ev0.y * kv.y + ev0.z * kv.z + ev0.w * kv.w;
        acc1 += ev1.x * kv.x + ev1.y * kv.y + ev1.z * kv.z + ev1.w * kv.w;
    }
#pragma unroll
    for (int o = 16; o; o >>= 1) {
        acc0 += __shfl_xor_sync(0xffffffffu, acc0, o);
        acc1 += __shfl_xor_sync(0xffffffffu, acc1, o);
    }
    if (lane == 0) {
        float v0 = acc0 * 0.03125f;
        float v1 = acc1 * 0.03125f;
        if (mask[row] == 0)     v0 = -1e9f;
        if (mask[row + 1] == 0) v1 = -1e9f;
        g_w[row]     = v0;
        g_w[row + 1] = v1;
    }
}

// ---------------------------------------------------------------------------
// k5: z-sum + kF + softmax + writers, ONE launch. 5760 blocks x 256 threads.
//   [0,512)      z-sum (reads hidden under write stream)
//   [512,640)    kF split-K           (gates on g_zcnt[b]==32; low ids, early)
//   [640,4736)   attn writers         (never gate -> guaranteed drain)
//   [4736,5760)  out writers          (gate on g_fcnt[b]==8; highest ids, last)
// ---------------------------------------------------------------------------
__global__ void __launch_bounds__(256) k5_fused(
    const float* __restrict__ zin, const float* __restrict__ Wv,
    float* __restrict__ out)
{
    __shared__ __align__(16) float smem[640];   // z: 128 float4 red; kF: zs[64]
    __shared__ float red[8];
    __shared__ float s_max, s_inv;
    const int blk = blockIdx.x;
    const int t = threadIdx.x;

    if (blk < 512) {
        // ---------------- z-sum: (batch, 64-row chunk), 256 threads ----------
        const int b = blk >> 5;
        const int chunk = blk & 31;
        const int sub = t >> 7;               // 0..1
        const int col4 = t & 127;
        const float4* base = (const float4*)zin
            + ((size_t)b * LL + (size_t)chunk * 64 + sub) * (ZZ / 4) + col4;
        float4 acc = make_float4(0.f, 0.f, 0.f, 0.f);
#pragma unroll
        for (int i = 0; i < 32; ++i) {        // rows sub, sub+2, ... (stride 2)
            const float4 v = __ldcs(base + (size_t)i * 2 * (ZZ / 4));
            acc.x += v.x; acc.y += v.y; acc.z += v.z; acc.w += v.w;
        }
        float4* sred = (float4*)smem;
        if (sub == 1) sred[col4] = acc;
        __syncthreads();
        if (sub == 0) {
            const float4 p = sred[col4];
            acc.x += p.x; acc.y += p.y; acc.z += p.z; acc.w += p.w;
            ((float4*)g_part)[(chunk * BB + b) * (ZZ / 4) + col4] = acc;
        }
        __threadfence();
        __syncthreads();
        if (t == 0) atomicAdd(&g_zcnt[b], 1u);

    } else if (blk < 640) {
        // ---------------- kF: split-K S2 slice (waits z[b]) ------------------
        const int e = blk - 512;              // 0..127
        const int b = e >> 3;
        const int slice = e & 7;
        if (t == 0) {
            while (*(volatile unsigned*)&g_zcnt[b] < 32u) {}
            __threadfence();
        }
        __syncthreads();

        float* zs = smem;                     // [64]
        const int cl = t >> 2;                // 0..63
        const int sub = t & 3;                // 0..3
        const int c = 64 * slice + cl;
        float a = 0.f;
#pragma unroll
        for (int j = 0; j < 8; ++j)
            a += __ldcg(&g_part[((sub + 4 * j) * BB + b) * ZZ + c]);
#pragma unroll
        for (int o = 2; o; o >>= 1) a += __shfl_xor_sync(0xffffffffu, a, o);
        if (sub == 0) zs[cl] = a;
        __syncthreads();

        // two output columns per thread (t and t+256)
#pragma unroll
        for (int h = 0; h < 2; ++h) {
            const int tt = t + 256 * h;
            float s = 0.f;
            const float* wbase = Wv + (size_t)(64 * slice) * ZZ + tt;
#pragma unroll 8
            for (int c2 = 0; c2 < 64; ++c2)
                s += zs[c2] * wbase[(size_t)c2 * ZZ];
            g_S2[(slice * BB + b) * ZZ + tt] = s;
        }
        __threadfence();
        __syncthreads();
        if (t == 0) atomicAdd(&g_fcnt[b], 1u);

    } else {
        // ---------------- writers ----------
        const bool is_attn = (blk < 4736);
        const int wb = is_attn ? (blk - 640) : (blk - 4736);
        const int b = is_attn ? (wb >> 8) : (wb >> 6);

        if (!is_attn && t == 0) {
            while (*(volatile unsigned*)&g_fcnt[b] < 8u) {}
            __threadfence();
        }
        __syncthreads();

        // softmax stats over this batch's 2048 raw logits (free under stores)
        const int warp = t >> 5, lane = t & 31;
        float lg[8];
#pragma unroll
        for (int k = 0; k < 8; ++k) lg[k] = __ldg(&g_w[b * LL + k * 256 + t]);

        float m = lg[0];
#pragma unroll
        for (int k = 1; k < 8; ++k) m = fmaxf(m, lg[k]);
#pragma unroll
        for (int o = 16; o; o >>= 1) m = fmaxf(m, __shfl_xor_sync(0xffffffffu, m, o));
        if (lane == 0) red[warp] = m;
        __syncthreads();
        if (warp == 0 && lane < 8) {
            float v = red[lane];
#pragma unroll
            for (int o = 4; o; o >>= 1) v = fmaxf(v, __shfl_xor_sync(0xffu, v, o));
            if (lane == 0) s_max = v;
        }
        __syncthreads();
        const float M = s_max;

        float s = 0.f;
#pragma unroll
        for (int k = 0; k < 8; ++k) s += __expf(lg[k] - M);
#pragma unroll
        for (int o = 16; o; o >>= 1) s += __shfl_xor_sync(0xffffffffu, s, o);
        __syncthreads();
        if (lane == 0) red[warp] = s;
        __syncthreads();
        if (warp == 0 && lane < 8) {
            float v = red[lane];
#pragma unroll
            for (int o = 4; o; o >>= 1) v += __shfl_xor_sync(0xffu, v, o);
            if (lane == 0) s_inv = 1.f / v;
        }
        __syncthreads();
        const float inv = s_inv;

        if (is_attn) {
            const long long base = (long long)b * (LL * LL / 4)
                                 + (long long)(wb & 255) * 4096;
            const int rowbase = (int)(base >> 9);
            float4* attn4 = (float4*)(out + (size_t)BB * LL * ZZ);
            float w8[8];
#pragma unroll
            for (int j = 0; j < 8; ++j)
                w8[j] = __expf(__ldg(&g_w[rowbase + j]) - M) * inv;
#pragma unroll
            for (int k = 0; k < 16; ++k) {
                const float wv = w8[k >> 1];
                __stcs(attn4 + base + k * 256 + t, make_float4(wv, wv, wv, wv));
            }
        } else {
            const long long base = (long long)b * (LL * ZZ / 4)
                                 + (long long)(wb & 63) * 4096;
            const int rowbase = (int)(base >> 7);
            const int rsub = t >> 7;
            const int col = t & 127;
            const float4* S24 = (const float4*)g_S2;
            float4 sv = make_float4(0.f, 0.f, 0.f, 0.f);
#pragma unroll
            for (int k = 0; k < 8; ++k) {
                const float4 p = __ldcg(&S24[(k * BB + b) * (ZZ / 4) + col]);
                sv.x += p.x; sv.y += p.y; sv.z += p.z; sv.w += p.w;
            }
#pragma unroll
            for (int k = 0; k < 16; ++k) {
                const float wv = __expf(__ldg(&g_w[rowbase + 2 * k + rsub]) - M) * inv;
                __stcs((float4*)out + base + k * 256 + t,
                       make_float4(wv * sv.x, wv * sv.y, wv * sv.z, wv * sv.w));
            }
        }
    }
}

// ---------------------------------------------------------------------------
extern "C" void kernel_launch(void* const* d_in, const int* in_sizes, int n_in,
                              void* d_out, int out_size)
{
    const float* enc  = (const float*)d_in[0];
    const float* fin  = (const float*)d_in[1];
    const float* zseq = (const float*)d_in[2];
    const int*   mask = (const int*)  d_in[3];
    const float* Wq   = (const float*)d_in[4];
    const float* Wk   = (const float*)d_in[5];
    const float* Wv   = (const float*)d_in[6];
    float* out = (float*)d_out;

    k1_a<<<128, 512>>>(fin, Wk);              // kA (+ counter reset)
    k2_b<<<128, 512>>>(Wq);                   // kB batch-shared
    k3_logits<<<1024, 512>>>(enc, mask);      // logits (2 rows/warp)
    k5_fused<<<5760, 256>>>(zseq, Wv, out);   // z-sum + kF + softmax + writers
}